// round 8
// baseline (speedup 1.0000x reference)
#include <cuda_runtime.h>
#include <cuda_bf16.h>
#include <math.h>
#include <stdint.h>

// Problem constants
#define BB     8
#define KK     2048
#define DD     1024
#define NINNER 2048
#define MM     (BB * KK)      // 16384 rows
#define EPSV   1e-5f

// GEMM tiling
#define BM 128
#define BN 128
#define BK 32
#define PAD 8
#define LDSS (BK + PAD)       // 40 bf16 row stride in SMEM

// SMEM pipeline: 3 stages x 4 arrays (A_hi, A_lo, B_hi, B_lo)
#define ARR_BYTES   (BM * LDSS * 2)        // 10240
#define STAGE_BYTES (4 * ARR_BYTES)        // 40960
#define NSTAGE      3
#define SMEM_TOTAL  (NSTAGE * STAGE_BYTES) // 122880

// ---------------------------------------------------------------------------
// Scratch (allocation-free: __device__ globals) — ~616 MB total
// ---------------------------------------------------------------------------
__device__ __nv_bfloat16 g_hhi [(size_t)MM * DD];       // 32 MB
__device__ __nv_bfloat16 g_hlo [(size_t)MM * DD];       // 32 MB
__device__ __nv_bfloat16 g_uhi [(size_t)MM * NINNER];   // 64 MB  silu(u) hi
__device__ __nv_bfloat16 g_ulo [(size_t)MM * NINNER];   // 64 MB  silu(u) lo
__device__ float         g_zs  [(size_t)MM * NINNER];   // 128 MB silu(z)
__device__ float         g_lam [(size_t)MM * NINNER];   // 128 MB lambda
__device__ __nv_bfloat16 g_szhi[(size_t)MM * NINNER];   // 64 MB  s*silu(z) hi
__device__ __nv_bfloat16 g_szlo[(size_t)MM * NINNER];   // 64 MB  s*silu(z) lo
__device__ __nv_bfloat16 g_wihi[(size_t)2 * NINNER * DD];   // 8 MB
__device__ __nv_bfloat16 g_wilo[(size_t)2 * NINNER * DD];   // 8 MB
__device__ __nv_bfloat16 g_wdhi[(size_t)NINNER * NINNER];   // 8 MB
__device__ __nv_bfloat16 g_wdlo[(size_t)NINNER * NINNER];   // 8 MB
__device__ __nv_bfloat16 g_wohi[(size_t)DD * NINNER];       // 4 MB
__device__ __nv_bfloat16 g_wolo[(size_t)DD * NINNER];       // 4 MB

// ---------------------------------------------------------------------------
// Helpers
// ---------------------------------------------------------------------------
__device__ __forceinline__ uint32_t smem_u32(const void* p) {
    uint32_t a;
    asm("{ .reg .u64 t; cvta.to.shared.u64 t, %1; cvt.u32.u64 %0, t; }"
        : "=r"(a) : "l"(p));
    return a;
}

__device__ __forceinline__ void ldsm_x4(uint32_t* r, uint32_t addr) {
    asm volatile("ldmatrix.sync.aligned.m8n8.x4.shared.b16 {%0,%1,%2,%3}, [%4];"
        : "=r"(r[0]), "=r"(r[1]), "=r"(r[2]), "=r"(r[3]) : "r"(addr));
}

__device__ __forceinline__ void mma_bf16(float* c, const uint32_t* a, const uint32_t* b) {
    asm volatile(
        "mma.sync.aligned.m16n8k16.row.col.f32.bf16.bf16.f32 "
        "{%0,%1,%2,%3}, {%4,%5,%6,%7}, {%8,%9}, {%0,%1,%2,%3};"
        : "+f"(c[0]), "+f"(c[1]), "+f"(c[2]), "+f"(c[3])
        : "r"(a[0]), "r"(a[1]), "r"(a[2]), "r"(a[3]), "r"(b[0]), "r"(b[1]));
}

__device__ __forceinline__ void cp16(uint32_t saddr, const void* g) {
    asm volatile("cp.async.cg.shared.global [%0], [%1], 16;" :: "r"(saddr), "l"(g));
}
#define CP_COMMIT() asm volatile("cp.async.commit_group;")
#define CP_WAIT1()  asm volatile("cp.async.wait_group 1;")

__device__ __forceinline__ uint32_t packbf2(float lo, float hi) {
    __nv_bfloat162 t = __floats2bfloat162_rn(lo, hi);
    return reinterpret_cast<uint32_t&>(t);
}

// Split float4 -> bf16 hi (uint2) + bf16 lo residual (uint2)
__device__ __forceinline__ void split4(float4 v, uint2& h, uint2& l) {
    uint32_t h01 = packbf2(v.x, v.y);
    uint32_t h23 = packbf2(v.z, v.w);
    __nv_bfloat162 bh01 = reinterpret_cast<__nv_bfloat162&>(h01);
    __nv_bfloat162 bh23 = reinterpret_cast<__nv_bfloat162&>(h23);
    h = make_uint2(h01, h23);
    l = make_uint2(packbf2(v.x - __low2float(bh01), v.y - __high2float(bh01)),
                   packbf2(v.z - __low2float(bh23), v.w - __high2float(bh23)));
}

// ---------------------------------------------------------------------------
// Weight split: fp32 -> bf16 hi/lo (n multiple of 4)
// ---------------------------------------------------------------------------
__global__ __launch_bounds__(256) void split_kernel(
    const float* __restrict__ w, __nv_bfloat16* __restrict__ hi,
    __nv_bfloat16* __restrict__ lo, int n4)
{
    int i = blockIdx.x * blockDim.x + threadIdx.x;
    if (i >= n4) return;
    float4 v = reinterpret_cast<const float4*>(w)[i];
    uint2 h, l;
    split4(v, h, l);
    reinterpret_cast<uint2*>(hi)[i] = h;
    reinterpret_cast<uint2*>(lo)[i] = l;
}

// ---------------------------------------------------------------------------
// RMSNorm: one block per row (1024 floats), 256 threads -> bf16 hi/lo
// ---------------------------------------------------------------------------
__global__ __launch_bounds__(256) void rmsnorm_kernel(
    const float* __restrict__ x, const float* __restrict__ w,
    __nv_bfloat16* __restrict__ hhi, __nv_bfloat16* __restrict__ hlo)
{
    const int row = blockIdx.x;
    const int t   = threadIdx.x;
    float4 v = reinterpret_cast<const float4*>(x + (size_t)row * DD)[t];
    float ss = v.x * v.x + v.y * v.y + v.z * v.z + v.w * v.w;

    #pragma unroll
    for (int o = 16; o > 0; o >>= 1)
        ss += __shfl_xor_sync(0xFFFFFFFFu, ss, o);

    __shared__ float wsum[8];
    if ((t & 31) == 0) wsum[t >> 5] = ss;
    __syncthreads();

    float sum = 0.f;
    #pragma unroll
    for (int i = 0; i < 8; i++) sum += wsum[i];

    const float scale = rsqrtf(sum * (1.0f / DD) + EPSV);
    const float4 wv = reinterpret_cast<const float4*>(w)[t];
    float4 o;
    o.x = v.x * scale * wv.x;
    o.y = v.y * scale * wv.y;
    o.z = v.z * scale * wv.z;
    o.w = v.w * scale * wv.w;
    uint2 h, l;
    split4(o, h, l);
    reinterpret_cast<uint2*>(hhi + (size_t)row * DD)[t] = h;
    reinterpret_cast<uint2*>(hlo + (size_t)row * DD)[t] = l;
}

// ---------------------------------------------------------------------------
// mma.sync bf16x3 NT GEMM on pre-split hi/lo operands.
// C[M,N] = A[M,KD] * Bw[N,KD]^T, logical fp32 via hi*hi + hi*lo + lo*hi.
// 128x128x32 CTA tile, 8 warps (2m x 4n), warp tile 64x32 as 4x4 m16n8k16.
// cp.async 3-stage pipeline, one __syncthreads per K-tile.
//
// MODE 0: c <  NINNER -> (ohi,olo)[r,c] = split(silu(v))
//         c >= NINNER -> zout[r,c-NINNER] = silu(v)      (fp32)
// MODE 1: fout[r,c] = sigmoid(v + bias[c])               (row stride NINNER)
// MODE 2: fout[r,c] = resid[r,c] + v                     (row stride DD)
// ---------------------------------------------------------------------------
template <int MODE>
__global__ __launch_bounds__(256, 1) void gemm_mma(
    const __nv_bfloat16* __restrict__ Ahi, const __nv_bfloat16* __restrict__ Alo,
    const __nv_bfloat16* __restrict__ Bhi, const __nv_bfloat16* __restrict__ Blo,
    int KD,
    const float* __restrict__ bias, const float* __restrict__ resid,
    float* __restrict__ fout,
    __nv_bfloat16* __restrict__ ohi, __nv_bfloat16* __restrict__ olo,
    float* __restrict__ zout)
{
    extern __shared__ __align__(16) char smem[];
    const uint32_t sb = smem_u32(smem);

    const int tid  = threadIdx.x;
    const int lane = tid & 31;
    const int wid  = tid >> 5;
    const int warp_m = wid >> 2;   // 0..1  (64 rows each)
    const int warp_n = wid & 3;    // 0..3  (32 cols each)
    const int bm = blockIdx.y * BM;
    const int bn = blockIdx.x * BN;
    const int NT = KD / BK;

    // Copy mapping: thread -> (row, 16-col half); 2 chunks of 8 bf16 per array
    const int srow = tid >> 1;
    const int scol = (tid & 1) * 16;
    const __nv_bfloat16* gah = Ahi + (size_t)(bm + srow) * KD + scol;
    const __nv_bfloat16* gal = Alo + (size_t)(bm + srow) * KD + scol;
    const __nv_bfloat16* gbh = Bhi + (size_t)(bn + srow) * KD + scol;
    const __nv_bfloat16* gbl = Blo + (size_t)(bn + srow) * KD + scol;
    const uint32_t s_off = (uint32_t)(srow * LDSS + scol) * 2;

    // ldmatrix per-lane addressing (verified mapping from R6)
    const int a_row0 = warp_m * 64 + (lane & 15);
    const int a_kadd = (lane >> 4) * 8;
    const int b_row0 = warp_n * 32 + ((lane >> 4) & 1) * 8 + (lane & 7);
    const int b_kadd = ((lane >> 3) & 1) * 8;

    float acc[4][4][4];
    #pragma unroll
    for (int i = 0; i < 4; i++)
        #pragma unroll
        for (int j = 0; j < 4; j++)
            #pragma unroll
            for (int q = 0; q < 4; q++) acc[i][j][q] = 0.f;

    // issue copies for tile kt into stage
    auto issue = [&](int stage, int kt) {
        const int k0 = kt * BK;
        const uint32_t st = sb + stage * STAGE_BYTES + s_off;
        cp16(st,                 gah + k0);  cp16(st + 16,                 gah + k0 + 8);
        cp16(st + ARR_BYTES,     gal + k0);  cp16(st + ARR_BYTES + 16,     gal + k0 + 8);
        cp16(st + 2 * ARR_BYTES, gbh + k0);  cp16(st + 2 * ARR_BYTES + 16, gbh + k0 + 8);
        cp16(st + 3 * ARR_BYTES, gbl + k0);  cp16(st + 3 * ARR_BYTES + 16, gbl + k0 + 8);
    };

    issue(0, 0); CP_COMMIT();
    issue(1, 1); CP_COMMIT();

    int stage = 0;
    for (int kt = 0; kt < NT; kt++) {
        CP_WAIT1();
        __syncthreads();

        if (kt + 2 < NT) {
            int ns = stage + 2; if (ns >= NSTAGE) ns -= NSTAGE;
            issue(ns, kt + 2);
        }
        CP_COMMIT();

        const uint32_t ah_b = sb + stage * STAGE_BYTES;
        const uint32_t al_b = ah_b + ARR_BYTES;
        const uint32_t bh_b = ah_b + 2 * ARR_BYTES;
        const uint32_t bl_b = ah_b + 3 * ARR_BYTES;

        #pragma unroll
        for (int ks = 0; ks < 2; ks++) {
            uint32_t bh[4][2], bl[4][2];
            #pragma unroll
            for (int pair = 0; pair < 2; pair++) {
                const uint32_t off =
                    2u * ((b_row0 + pair * 16) * LDSS + ks * 16 + b_kadd);
                uint32_t r[4];
                ldsm_x4(r, bh_b + off);
                bh[pair * 2][0] = r[0]; bh[pair * 2][1] = r[1];
                bh[pair * 2 + 1][0] = r[2]; bh[pair * 2 + 1][1] = r[3];
                ldsm_x4(r, bl_b + off);
                bl[pair * 2][0] = r[0]; bl[pair * 2][1] = r[1];
                bl[pair * 2 + 1][0] = r[2]; bl[pair * 2 + 1][1] = r[3];
            }
            #pragma unroll
            for (int mt = 0; mt < 4; mt++) {
                const uint32_t off =
                    2u * ((a_row0 + mt * 16) * LDSS + ks * 16 + a_kadd);
                uint32_t ah[4], al[4];
                ldsm_x4(ah, ah_b + off);
                ldsm_x4(al, al_b + off);
                #pragma unroll
                for (int nt = 0; nt < 4; nt++) {
                    mma_bf16(acc[mt][nt], ah, bh[nt]);
                    mma_bf16(acc[mt][nt], ah, bl[nt]);
                    mma_bf16(acc[mt][nt], al, bh[nt]);
                }
            }
        }

        stage++; if (stage >= NSTAGE) stage = 0;
    }

    // Epilogue straight from accumulators.
    const int er = bm + warp_m * 64 + (lane >> 2);
    const int ec = bn + warp_n * 32 + (lane & 3) * 2;

    #pragma unroll
    for (int mt = 0; mt < 4; mt++) {
        #pragma unroll
        for (int nt = 0; nt < 4; nt++) {
            #pragma unroll
            for (int half = 0; half < 2; half++) {
                const int r = er + mt * 16 + half * 8;
                const int c = ec + nt * 8;
                float v0 = acc[mt][nt][half * 2 + 0];
                float v1 = acc[mt][nt][half * 2 + 1];
                if (MODE == 0) {
                    float s0 = v0 / (1.0f + expf(-v0));
                    float s1 = v1 / (1.0f + expf(-v1));
                    if (bn < NINNER) {
                        // split to bf16 hi/lo for GEMM2 / scan
                        uint32_t h = packbf2(s0, s1);
                        __nv_bfloat162 bh2 = reinterpret_cast<__nv_bfloat162&>(h);
                        uint32_t l = packbf2(s0 - __low2float(bh2), s1 - __high2float(bh2));
                        *reinterpret_cast<uint32_t*>(ohi + (size_t)r * NINNER + c) = h;
                        *reinterpret_cast<uint32_t*>(olo + (size_t)r * NINNER + c) = l;
                    } else {
                        float2 o = make_float2(s0, s1);
                        *reinterpret_cast<float2*>(zout + (size_t)r * NINNER + (c - NINNER)) = o;
                    }
                } else if (MODE == 1) {
                    float2 bv = *reinterpret_cast<const float2*>(bias + c);
                    float2 o;
                    o.x = 1.0f / (1.0f + expf(-(v0 + bv.x)));
                    o.y = 1.0f / (1.0f + expf(-(v1 + bv.y)));
                    *reinterpret_cast<float2*>(fout + (size_t)r * NINNER + c) = o;
                } else {
                    float2 rv = *reinterpret_cast<const float2*>(resid + (size_t)r * DD + c);
                    float2 o;
                    o.x = rv.x + v0;
                    o.y = rv.y + v1;
                    *reinterpret_cast<float2*>(fout + (size_t)r * DD + c) = o;
                }
            }
        }
    }
}

// ---------------------------------------------------------------------------
// Sequential scan over K per (batch, channel):  s_k = u_k + lam_k*(s_{k-1}-u_k)
// u reconstructed from hi+lo; output s*silu(z) split to bf16 hi/lo.
// ---------------------------------------------------------------------------
__global__ __launch_bounds__(256) void scan_kernel(
    const float* __restrict__ lam,
    const __nv_bfloat16* __restrict__ uhi, const __nv_bfloat16* __restrict__ ulo,
    const float* __restrict__ zs,
    __nv_bfloat16* __restrict__ szhi, __nv_bfloat16* __restrict__ szlo)
{
    const int idx = blockIdx.x * blockDim.x + threadIdx.x;  // 0..16383
    const int b = idx >> 11;
    const int j = idx & (NINNER - 1);
    size_t off = ((size_t)b * KK) * NINNER + j;
    float s = 0.f;
    #pragma unroll 8
    for (int k = 0; k < KK; k++) {
        const float l  = __ldg(lam + off);
        const float uu = __bfloat162float(__ldg(uhi + off)) +
                         __bfloat162float(__ldg(ulo + off));
        const float zz = __ldg(zs + off);
        s = fmaf(l, s - uu, uu);
        const float val = s * zz;
        const __nv_bfloat16 h = __float2bfloat16(val);
        szhi[off] = h;
        szlo[off] = __float2bfloat16(val - __bfloat162float(h));
        off += NINNER;
    }
}

// ---------------------------------------------------------------------------
// Launch
// ---------------------------------------------------------------------------
extern "C" void kernel_launch(void* const* d_in, const int* in_sizes, int n_in,
                              void* d_out, int out_size)
{
    const float* x      = (const float*)d_in[0];
    const float* w_norm = (const float*)d_in[1];
    const float* W_in   = (const float*)d_in[2];   // [2*NINNER, DD]
    const float* W_dt   = (const float*)d_in[3];   // [NINNER, NINNER]
    const float* b_dt   = (const float*)d_in[4];   // [NINNER]
    const float* W_out  = (const float*)d_in[5];   // [DD, NINNER]
    float* out = (float*)d_out;

    __nv_bfloat16 *hhi, *hlo, *uhi, *ulo, *szhi, *szlo;
    __nv_bfloat16 *wihi, *wilo, *wdhi, *wdlo, *wohi, *wolo;
    float *zs, *lam;
    cudaGetSymbolAddress((void**)&hhi,  g_hhi);
    cudaGetSymbolAddress((void**)&hlo,  g_hlo);
    cudaGetSymbolAddress((void**)&uhi,  g_uhi);
    cudaGetSymbolAddress((void**)&ulo,  g_ulo);
    cudaGetSymbolAddress((void**)&zs,   g_zs);
    cudaGetSymbolAddress((void**)&lam,  g_lam);
    cudaGetSymbolAddress((void**)&szhi, g_szhi);
    cudaGetSymbolAddress((void**)&szlo, g_szlo);
    cudaGetSymbolAddress((void**)&wihi, g_wihi);
    cudaGetSymbolAddress((void**)&wilo, g_wilo);
    cudaGetSymbolAddress((void**)&wdhi, g_wdhi);
    cudaGetSymbolAddress((void**)&wdlo, g_wdlo);
    cudaGetSymbolAddress((void**)&wohi, g_wohi);
    cudaGetSymbolAddress((void**)&wolo, g_wolo);

    cudaFuncSetAttribute(gemm_mma<0>, cudaFuncAttributeMaxDynamicSharedMemorySize, SMEM_TOTAL);
    cudaFuncSetAttribute(gemm_mma<1>, cudaFuncAttributeMaxDynamicSharedMemorySize, SMEM_TOTAL);
    cudaFuncSetAttribute(gemm_mma<2>, cudaFuncAttributeMaxDynamicSharedMemorySize, SMEM_TOTAL);

    // 0. Split weights into bf16 hi/lo
    split_kernel<<<(2 * NINNER * DD / 4 + 255) / 256, 256>>>(W_in,  wihi, wilo, 2 * NINNER * DD / 4);
    split_kernel<<<(NINNER * NINNER / 4 + 255) / 256, 256>>>(W_dt,  wdhi, wdlo, NINNER * NINNER / 4);
    split_kernel<<<(DD * NINNER / 4 + 255) / 256, 256>>>(W_out, wohi, wolo, DD * NINNER / 4);

    // 1. RMSNorm -> h hi/lo
    rmsnorm_kernel<<<MM, 256>>>(x, w_norm, hhi, hlo);

    // 2. uv = h @ W_in^T ; split + silu   (M=16384, N=4096, KD=1024)
    {
        dim3 grid((2 * NINNER) / BN, MM / BM);
        gemm_mma<0><<<grid, 256, SMEM_TOTAL>>>(hhi, hlo, wihi, wilo, DD,
                                               nullptr, nullptr, nullptr, uhi, ulo, zs);
    }

    // 3. lam = sigmoid(u @ W_dt^T + b_dt)   (M=16384, N=2048, KD=2048)
    {
        dim3 grid(NINNER / BN, MM / BM);
        gemm_mma<1><<<grid, 256, SMEM_TOTAL>>>(uhi, ulo, wdhi, wdlo, NINNER,
                                               b_dt, nullptr, lam, nullptr, nullptr, nullptr);
    }

    // 4. scan -> sz hi/lo
    scan_kernel<<<MM / 256, 256>>>(lam, uhi, ulo, zs, szhi, szlo);

    // 5. y = sz @ W_out^T + x   (M=16384, N=1024, KD=2048)
    {
        dim3 grid(DD / BN, MM / BM);
        gemm_mma<2><<<grid, 256, SMEM_TOTAL>>>(szhi, szlo, wohi, wolo, NINNER,
                                               nullptr, x, out, nullptr, nullptr, nullptr);
    }
}

// round 11
// speedup vs baseline: 1.0505x; 1.0505x over previous
#include <cuda_runtime.h>
#include <cuda_bf16.h>
#include <math.h>
#include <stdint.h>

// Problem constants
#define BB     8
#define KK     2048
#define DD     1024
#define NINNER 2048
#define MM     (BB * KK)      // 16384 rows
#define EPSV   1e-5f

// GEMM tiling
#define BM 128
#define BN 128
#define BK 64
#define PAD 8
#define LDSS (BK + PAD)       // 72 bf16 row stride in SMEM

// SMEM pipeline: 3 stages x 4 arrays (A_hi, A_lo, B_hi, B_lo)
#define ARR_BYTES   (BM * LDSS * 2)        // 18432
#define STAGE_BYTES (4 * ARR_BYTES)        // 73728
#define NSTAGE      3
#define SMEM_TOTAL  (NSTAGE * STAGE_BYTES) // 221184

// Scan chunking
#define NCH   16
#define CHUNK (KK / NCH)      // 128

// ---------------------------------------------------------------------------
// Scratch (allocation-free: __device__ globals)
// ---------------------------------------------------------------------------
__device__ __nv_bfloat16 g_hhi [(size_t)MM * DD];       // 32 MB
__device__ __nv_bfloat16 g_hlo [(size_t)MM * DD];       // 32 MB
__device__ __nv_bfloat16 g_uhi [(size_t)MM * NINNER];   // 64 MB  silu(u) hi
__device__ __nv_bfloat16 g_ulo [(size_t)MM * NINNER];   // 64 MB  silu(u) lo
__device__ float         g_zs  [(size_t)MM * NINNER];   // 128 MB silu(z)
__device__ float         g_lam [(size_t)MM * NINNER];   // 128 MB lambda
__device__ __nv_bfloat16 g_szhi[(size_t)MM * NINNER];   // 64 MB  s*silu(z) hi
__device__ __nv_bfloat16 g_szlo[(size_t)MM * NINNER];   // 64 MB  s*silu(z) lo
__device__ __nv_bfloat16 g_wihi[(size_t)2 * NINNER * DD];   // 8 MB
__device__ __nv_bfloat16 g_wilo[(size_t)2 * NINNER * DD];   // 8 MB
__device__ __nv_bfloat16 g_wdhi[(size_t)NINNER * NINNER];   // 8 MB
__device__ __nv_bfloat16 g_wdlo[(size_t)NINNER * NINNER];   // 8 MB
__device__ __nv_bfloat16 g_wohi[(size_t)DD * NINNER];       // 4 MB
__device__ __nv_bfloat16 g_wolo[(size_t)DD * NINNER];       // 4 MB
__device__ float g_P[(size_t)BB * NCH * NINNER];            // 1 MB
__device__ float g_Q[(size_t)BB * NCH * NINNER];            // 1 MB
__device__ float g_S[(size_t)BB * NCH * NINNER];            // 1 MB

// ---------------------------------------------------------------------------
// Helpers
// ---------------------------------------------------------------------------
__device__ __forceinline__ uint32_t smem_u32(const void* p) {
    uint32_t a;
    asm("{ .reg .u64 t; cvta.to.shared.u64 t, %1; cvt.u32.u64 %0, t; }"
        : "=r"(a) : "l"(p));
    return a;
}

__device__ __forceinline__ void ldsm_x4(uint32_t* r, uint32_t addr) {
    asm volatile("ldmatrix.sync.aligned.m8n8.x4.shared.b16 {%0,%1,%2,%3}, [%4];"
        : "=r"(r[0]), "=r"(r[1]), "=r"(r[2]), "=r"(r[3]) : "r"(addr));
}

__device__ __forceinline__ void mma_bf16(float* c, const uint32_t* a, const uint32_t* b) {
    asm volatile(
        "mma.sync.aligned.m16n8k16.row.col.f32.bf16.bf16.f32 "
        "{%0,%1,%2,%3}, {%4,%5,%6,%7}, {%8,%9}, {%0,%1,%2,%3};"
        : "+f"(c[0]), "+f"(c[1]), "+f"(c[2]), "+f"(c[3])
        : "r"(a[0]), "r"(a[1]), "r"(a[2]), "r"(a[3]), "r"(b[0]), "r"(b[1]));
}

__device__ __forceinline__ void cp16(uint32_t saddr, const void* g) {
    asm volatile("cp.async.cg.shared.global [%0], [%1], 16;" :: "r"(saddr), "l"(g));
}
#define CP_COMMIT() asm volatile("cp.async.commit_group;")
#define CP_WAIT1()  asm volatile("cp.async.wait_group 1;")

__device__ __forceinline__ uint32_t packbf2(float lo, float hi) {
    __nv_bfloat162 t = __floats2bfloat162_rn(lo, hi);
    return reinterpret_cast<uint32_t&>(t);
}

// Split float4 -> bf16 hi (uint2) + bf16 lo residual (uint2)
__device__ __forceinline__ void split4(float4 v, uint2& h, uint2& l) {
    uint32_t h01 = packbf2(v.x, v.y);
    uint32_t h23 = packbf2(v.z, v.w);
    __nv_bfloat162 bh01 = reinterpret_cast<__nv_bfloat162&>(h01);
    __nv_bfloat162 bh23 = reinterpret_cast<__nv_bfloat162&>(h23);
    h = make_uint2(h01, h23);
    l = make_uint2(packbf2(v.x - __low2float(bh01), v.y - __high2float(bh01)),
                   packbf2(v.z - __low2float(bh23), v.w - __high2float(bh23)));
}

// ---------------------------------------------------------------------------
// Weight split: fp32 -> bf16 hi/lo (n multiple of 4)
// ---------------------------------------------------------------------------
__global__ __launch_bounds__(256) void split_kernel(
    const float* __restrict__ w, __nv_bfloat16* __restrict__ hi,
    __nv_bfloat16* __restrict__ lo, int n4)
{
    int i = blockIdx.x * blockDim.x + threadIdx.x;
    if (i >= n4) return;
    float4 v = reinterpret_cast<const float4*>(w)[i];
    uint2 h, l;
    split4(v, h, l);
    reinterpret_cast<uint2*>(hi)[i] = h;
    reinterpret_cast<uint2*>(lo)[i] = l;
}

// ---------------------------------------------------------------------------
// RMSNorm: one block per row (1024 floats), 256 threads -> bf16 hi/lo
// ---------------------------------------------------------------------------
__global__ __launch_bounds__(256) void rmsnorm_kernel(
    const float* __restrict__ x, const float* __restrict__ w,
    __nv_bfloat16* __restrict__ hhi, __nv_bfloat16* __restrict__ hlo)
{
    const int row = blockIdx.x;
    const int t   = threadIdx.x;
    float4 v = reinterpret_cast<const float4*>(x + (size_t)row * DD)[t];
    float ss = v.x * v.x + v.y * v.y + v.z * v.z + v.w * v.w;

    #pragma unroll
    for (int o = 16; o > 0; o >>= 1)
        ss += __shfl_xor_sync(0xFFFFFFFFu, ss, o);

    __shared__ float wsum[8];
    if ((t & 31) == 0) wsum[t >> 5] = ss;
    __syncthreads();

    float sum = 0.f;
    #pragma unroll
    for (int i = 0; i < 8; i++) sum += wsum[i];

    const float scale = rsqrtf(sum * (1.0f / DD) + EPSV);
    const float4 wv = reinterpret_cast<const float4*>(w)[t];
    float4 o;
    o.x = v.x * scale * wv.x;
    o.y = v.y * scale * wv.y;
    o.z = v.z * scale * wv.z;
    o.w = v.w * scale * wv.w;
    uint2 h, l;
    split4(o, h, l);
    reinterpret_cast<uint2*>(hhi + (size_t)row * DD)[t] = h;
    reinterpret_cast<uint2*>(hlo + (size_t)row * DD)[t] = l;
}

// ---------------------------------------------------------------------------
// mma.sync bf16x3 NT GEMM on pre-split hi/lo operands.  SINGLE instantiation,
// runtime mode switch in the (tiny) epilogue; ks loop NOT unrolled to keep
// compiled size small.
//
// C[M,N] = A[M,KD] * Bw[N,KD]^T, logical fp32 via hi*hi + hi*lo + lo*hi.
// 128x128x64 CTA tile, 8 warps (2m x 4n), warp tile 64x32 as 4x4 m16n8k16.
// cp.async 3-stage ring, ONE __syncthreads per 64-K tile.
//
// mode 0: c <  NINNER -> (ohi,olo)[r,c] = split(silu(v))
//         c >= NINNER -> zout[r,c-NINNER] = silu(v)      (fp32)
// mode 1: fout[r,c] = sigmoid(v + bias[c])               (row stride NINNER)
// mode 2: fout[r,c] = resid[r,c] + v                     (row stride DD)
// ---------------------------------------------------------------------------
__global__ __launch_bounds__(256, 1) void gemm_mma(
    const __nv_bfloat16* __restrict__ Ahi, const __nv_bfloat16* __restrict__ Alo,
    const __nv_bfloat16* __restrict__ Bhi, const __nv_bfloat16* __restrict__ Blo,
    int KD, int mode,
    const float* __restrict__ bias, const float* __restrict__ resid,
    float* __restrict__ fout,
    __nv_bfloat16* __restrict__ ohi, __nv_bfloat16* __restrict__ olo,
    float* __restrict__ zout)
{
    extern __shared__ __align__(16) char smem[];
    const uint32_t sb = smem_u32(smem);

    const int tid  = threadIdx.x;
    const int lane = tid & 31;
    const int wid  = tid >> 5;
    const int warp_m = wid >> 2;   // 0..1  (64 rows each)
    const int warp_n = wid & 3;    // 0..3  (32 cols each)
    const int bm = blockIdx.y * BM;
    const int bn = blockIdx.x * BN;
    const int NT = KD / BK;

    // Copy mapping: thread -> (row, 32-col half); 4 cp16 chunks per array
    const int srow = tid >> 1;
    const int scol = (tid & 1) * 32;
    const __nv_bfloat16* gah = Ahi + (size_t)(bm + srow) * KD + scol;
    const __nv_bfloat16* gal = Alo + (size_t)(bm + srow) * KD + scol;
    const __nv_bfloat16* gbh = Bhi + (size_t)(bn + srow) * KD + scol;
    const __nv_bfloat16* gbl = Blo + (size_t)(bn + srow) * KD + scol;
    const uint32_t s_off = (uint32_t)(srow * LDSS + scol) * 2;

    // ldmatrix per-lane addressing (verified mapping, R6)
    const int a_row0 = warp_m * 64 + (lane & 15);
    const int a_kadd = (lane >> 4) * 8;
    const int b_row0 = warp_n * 32 + ((lane >> 4) & 1) * 8 + (lane & 7);
    const int b_kadd = ((lane >> 3) & 1) * 8;

    float acc[4][4][4];
    #pragma unroll
    for (int i = 0; i < 4; i++)
        #pragma unroll
        for (int j = 0; j < 4; j++)
            #pragma unroll
            for (int q = 0; q < 4; q++) acc[i][j][q] = 0.f;

    // issue copies for tile kt into stage (each array: 4 cp16 = 64B/thread)
    auto issue = [&](int stage, int kt) {
        const int k0 = kt * BK;
        const uint32_t st = sb + stage * STAGE_BYTES + s_off;
        #pragma unroll
        for (int q = 0; q < 4; q++) {
            cp16(st + q * 16,                 gah + k0 + q * 8);
            cp16(st + ARR_BYTES + q * 16,     gal + k0 + q * 8);
            cp16(st + 2 * ARR_BYTES + q * 16, gbh + k0 + q * 8);
            cp16(st + 3 * ARR_BYTES + q * 16, gbl + k0 + q * 8);
        }
    };

    issue(0, 0); CP_COMMIT();
    issue(1, 1); CP_COMMIT();

    int stage = 0;
    for (int kt = 0; kt < NT; kt++) {
        CP_WAIT1();
        __syncthreads();

        if (kt + 2 < NT) {
            int ns = stage + 2; if (ns >= NSTAGE) ns -= NSTAGE;
            issue(ns, kt + 2);
        }
        CP_COMMIT();

        const uint32_t ah_b = sb + stage * STAGE_BYTES;
        const uint32_t al_b = ah_b + ARR_BYTES;
        const uint32_t bh_b = ah_b + 2 * ARR_BYTES;
        const uint32_t bl_b = ah_b + 3 * ARR_BYTES;

        #pragma unroll 1
        for (int ks = 0; ks < 4; ks++) {
            uint32_t bh[4][2], bl[4][2];
            #pragma unroll
            for (int pair = 0; pair < 2; pair++) {
                const uint32_t off =
                    2u * ((b_row0 + pair * 16) * LDSS + ks * 16 + b_kadd);
                uint32_t r[4];
                ldsm_x4(r, bh_b + off);
                bh[pair * 2][0] = r[0]; bh[pair * 2][1] = r[1];
                bh[pair * 2 + 1][0] = r[2]; bh[pair * 2 + 1][1] = r[3];
                ldsm_x4(r, bl_b + off);
                bl[pair * 2][0] = r[0]; bl[pair * 2][1] = r[1];
                bl[pair * 2 + 1][0] = r[2]; bl[pair * 2 + 1][1] = r[3];
            }
            #pragma unroll
            for (int mt = 0; mt < 4; mt++) {
                const uint32_t off =
                    2u * ((a_row0 + mt * 16) * LDSS + ks * 16 + a_kadd);
                uint32_t ah[4], al[4];
                ldsm_x4(ah, ah_b + off);
                ldsm_x4(al, al_b + off);
                #pragma unroll
                for (int nt = 0; nt < 4; nt++) {
                    mma_bf16(acc[mt][nt], ah, bh[nt]);
                    mma_bf16(acc[mt][nt], ah, bl[nt]);
                    mma_bf16(acc[mt][nt], al, bh[nt]);
                }
            }
        }

        stage++; if (stage >= NSTAGE) stage = 0;
    }

    // Epilogue straight from accumulators (uniform runtime mode branch).
    const int er = bm + warp_m * 64 + (lane >> 2);
    const int ec = bn + warp_n * 32 + (lane & 3) * 2;

    #pragma unroll
    for (int mt = 0; mt < 4; mt++) {
        #pragma unroll
        for (int nt = 0; nt < 4; nt++) {
            #pragma unroll
            for (int half = 0; half < 2; half++) {
                const int r = er + mt * 16 + half * 8;
                const int c = ec + nt * 8;
                float v0 = acc[mt][nt][half * 2 + 0];
                float v1 = acc[mt][nt][half * 2 + 1];
                if (mode == 0) {
                    float s0 = v0 / (1.0f + expf(-v0));
                    float s1 = v1 / (1.0f + expf(-v1));
                    if (bn < NINNER) {
                        uint32_t h = packbf2(s0, s1);
                        __nv_bfloat162 bh2 = reinterpret_cast<__nv_bfloat162&>(h);
                        uint32_t l = packbf2(s0 - __low2float(bh2), s1 - __high2float(bh2));
                        *reinterpret_cast<uint32_t*>(ohi + (size_t)r * NINNER + c) = h;
                        *reinterpret_cast<uint32_t*>(olo + (size_t)r * NINNER + c) = l;
                    } else {
                        float2 o = make_float2(s0, s1);
                        *reinterpret_cast<float2*>(zout + (size_t)r * NINNER + (c - NINNER)) = o;
                    }
                } else if (mode == 1) {
                    float2 bv = *reinterpret_cast<const float2*>(bias + c);
                    float2 o;
                    o.x = 1.0f / (1.0f + expf(-(v0 + bv.x)));
                    o.y = 1.0f / (1.0f + expf(-(v1 + bv.y)));
                    *reinterpret_cast<float2*>(fout + (size_t)r * NINNER + c) = o;
                } else {
                    float2 rv = *reinterpret_cast<const float2*>(resid + (size_t)r * DD + c);
                    float2 o;
                    o.x = rv.x + v0;
                    o.y = rv.y + v1;
                    *reinterpret_cast<float2*>(fout + (size_t)r * DD + c) = o;
                }
            }
        }
    }
}

// ---------------------------------------------------------------------------
// Parallel chunked scan.  s_k = u_k + lam_k*(s_{k-1}-u_k)  over K=2048,
// split into NCH=16 chunks of 128.  Affine composition: s_out = P*s_in + Q.
// ---------------------------------------------------------------------------
// Phase 1: per (b, chunk, j) compute P = prod(lam), Q = chunk scan from 0.
__global__ __launch_bounds__(256) void scan_p1(
    const float* __restrict__ lam,
    const __nv_bfloat16* __restrict__ uhi, const __nv_bfloat16* __restrict__ ulo,
    float* __restrict__ Pb, float* __restrict__ Qb)
{
    const int idx = blockIdx.x * blockDim.x + threadIdx.x;  // b*NCH*NINNER layout
    const int j   = idx & (NINNER - 1);
    const int bc  = idx >> 11;              // b * NCH + c
    const int b   = bc >> 4;
    const int c   = bc & (NCH - 1);
    size_t off = ((size_t)(b * KK + c * CHUNK)) * NINNER + j;
    float P = 1.f, Q = 0.f;
    #pragma unroll 8
    for (int k = 0; k < CHUNK; k++) {
        const float l  = __ldg(lam + off);
        const float uu = __bfloat162float(__ldg(uhi + off)) +
                         __bfloat162float(__ldg(ulo + off));
        Q = fmaf(l, Q - uu, uu);
        P *= l;
        off += NINNER;
    }
    Pb[idx] = P;
    Qb[idx] = Q;
}

// Phase 2: per (b, j) scan the 16 chunk summaries -> entry state per chunk.
__global__ __launch_bounds__(256) void scan_p2(
    const float* __restrict__ Pb, const float* __restrict__ Qb,
    float* __restrict__ Sb)
{
    const int idx = blockIdx.x * blockDim.x + threadIdx.x;  // 0..16383
    const int b = idx >> 11;
    const int j = idx & (NINNER - 1);
    float s = 0.f;
    #pragma unroll
    for (int c = 0; c < NCH; c++) {
        const size_t o = ((size_t)(b * NCH + c)) * NINNER + j;
        Sb[o] = s;
        s = fmaf(Pb[o], s, Qb[o]);
    }
}

// Phase 3: replay each chunk with its entry state; write s*silu(z) hi/lo.
__global__ __launch_bounds__(256) void scan_p3(
    const float* __restrict__ lam,
    const __nv_bfloat16* __restrict__ uhi, const __nv_bfloat16* __restrict__ ulo,
    const float* __restrict__ zs, const float* __restrict__ Sb,
    __nv_bfloat16* __restrict__ szhi, __nv_bfloat16* __restrict__ szlo)
{
    const int idx = blockIdx.x * blockDim.x + threadIdx.x;
    const int j   = idx & (NINNER - 1);
    const int bc  = idx >> 11;
    const int b   = bc >> 4;
    const int c   = bc & (NCH - 1);
    size_t off = ((size_t)(b * KK + c * CHUNK)) * NINNER + j;
    float s = Sb[idx];
    #pragma unroll 8
    for (int k = 0; k < CHUNK; k++) {
        const float l  = __ldg(lam + off);
        const float uu = __bfloat162float(__ldg(uhi + off)) +
                         __bfloat162float(__ldg(ulo + off));
        const float zz = __ldg(zs + off);
        s = fmaf(l, s - uu, uu);
        const float val = s * zz;
        const __nv_bfloat16 h = __float2bfloat16(val);
        szhi[off] = h;
        szlo[off] = __float2bfloat16(val - __bfloat162float(h));
        off += NINNER;
    }
}

// ---------------------------------------------------------------------------
// Launch
// ---------------------------------------------------------------------------
extern "C" void kernel_launch(void* const* d_in, const int* in_sizes, int n_in,
                              void* d_out, int out_size)
{
    const float* x      = (const float*)d_in[0];
    const float* w_norm = (const float*)d_in[1];
    const float* W_in   = (const float*)d_in[2];   // [2*NINNER, DD]
    const float* W_dt   = (const float*)d_in[3];   // [NINNER, NINNER]
    const float* b_dt   = (const float*)d_in[4];   // [NINNER]
    const float* W_out  = (const float*)d_in[5];   // [DD, NINNER]
    float* out = (float*)d_out;

    __nv_bfloat16 *hhi, *hlo, *uhi, *ulo, *szhi, *szlo;
    __nv_bfloat16 *wihi, *wilo, *wdhi, *wdlo, *wohi, *wolo;
    float *zs, *lam, *Pb, *Qb, *Sb;
    cudaGetSymbolAddress((void**)&hhi,  g_hhi);
    cudaGetSymbolAddress((void**)&hlo,  g_hlo);
    cudaGetSymbolAddress((void**)&uhi,  g_uhi);
    cudaGetSymbolAddress((void**)&ulo,  g_ulo);
    cudaGetSymbolAddress((void**)&zs,   g_zs);
    cudaGetSymbolAddress((void**)&lam,  g_lam);
    cudaGetSymbolAddress((void**)&szhi, g_szhi);
    cudaGetSymbolAddress((void**)&szlo, g_szlo);
    cudaGetSymbolAddress((void**)&wihi, g_wihi);
    cudaGetSymbolAddress((void**)&wilo, g_wilo);
    cudaGetSymbolAddress((void**)&wdhi, g_wdhi);
    cudaGetSymbolAddress((void**)&wdlo, g_wdlo);
    cudaGetSymbolAddress((void**)&wohi, g_wohi);
    cudaGetSymbolAddress((void**)&wolo, g_wolo);
    cudaGetSymbolAddress((void**)&Pb,   g_P);
    cudaGetSymbolAddress((void**)&Qb,   g_Q);
    cudaGetSymbolAddress((void**)&Sb,   g_S);

    cudaFuncSetAttribute(gemm_mma, cudaFuncAttributeMaxDynamicSharedMemorySize, SMEM_TOTAL);

    // 0. Split weights into bf16 hi/lo
    split_kernel<<<(2 * NINNER * DD / 4 + 255) / 256, 256>>>(W_in,  wihi, wilo, 2 * NINNER * DD / 4);
    split_kernel<<<(NINNER * NINNER / 4 + 255) / 256, 256>>>(W_dt,  wdhi, wdlo, NINNER * NINNER / 4);
    split_kernel<<<(DD * NINNER / 4 + 255) / 256, 256>>>(W_out, wohi, wolo, DD * NINNER / 4);

    // 1. RMSNorm -> h hi/lo
    rmsnorm_kernel<<<MM, 256>>>(x, w_norm, hhi, hlo);

    // 2. uv = h @ W_in^T ; split + silu   (M=16384, N=4096, KD=1024)
    {
        dim3 grid((2 * NINNER) / BN, MM / BM);
        gemm_mma<<<grid, 256, SMEM_TOTAL>>>(hhi, hlo, wihi, wilo, DD, 0,
                                            nullptr, nullptr, nullptr, uhi, ulo, zs);
    }

    // 3. lam = sigmoid(u @ W_dt^T + b_dt)   (M=16384, N=2048, KD=2048)
    {
        dim3 grid(NINNER / BN, MM / BM);
        gemm_mma<<<grid, 256, SMEM_TOTAL>>>(uhi, ulo, wdhi, wdlo, NINNER, 1,
                                            b_dt, nullptr, lam, nullptr, nullptr, nullptr);
    }

    // 4. parallel chunked scan -> sz hi/lo
    scan_p1<<<BB * NCH * NINNER / 256, 256>>>(lam, uhi, ulo, Pb, Qb);
    scan_p2<<<BB * NINNER / 256, 256>>>(Pb, Qb, Sb);
    scan_p3<<<BB * NCH * NINNER / 256, 256>>>(lam, uhi, ulo, zs, Sb, szhi, szlo);

    // 5. y = sz @ W_out^T + x   (M=16384, N=1024, KD=2048)
    {
        dim3 grid(DD / BN, MM / BM);
        gemm_mma<<<grid, 256, SMEM_TOTAL>>>(szhi, szlo, wohi, wolo, NINNER, 2,
                                            nullptr, x, out, nullptr, nullptr, nullptr);
    }
}

// round 12
// speedup vs baseline: 2.3320x; 2.2200x over previous
#include <cuda_runtime.h>
#include <cuda_fp16.h>
#include <math.h>
#include <stdint.h>

// Problem constants
#define BB     8
#define KK     2048
#define DD     1024
#define NINNER 2048
#define MM     (BB * KK)      // 16384 rows
#define EPSV   1e-5f

// GEMM tiling
#define BM 128
#define BN 128
#define BK 64
#define PAD 8
#define LDSS (BK + PAD)       // 72 fp16 row stride in SMEM

// SMEM pipeline: 4 stages x 2 arrays (A, B)
#define ARR_BYTES   (BM * LDSS * 2)        // 18432
#define STAGE_BYTES (2 * ARR_BYTES)        // 36864
#define NSTAGE      4
#define SMEM_TOTAL  (NSTAGE * STAGE_BYTES) // 147456

// Scan chunking
#define NCH   16
#define CHUNK (KK / NCH)      // 128

// ---------------------------------------------------------------------------
// Scratch (allocation-free: __device__ globals)
// ---------------------------------------------------------------------------
__device__ __half g_h16 [(size_t)MM * DD];       // 32 MB  rmsnorm out (fp16)
__device__ __half g_u16 [(size_t)MM * NINNER];   // 64 MB  silu(u) fp16 (GEMM2 A)
__device__ float  g_uf  [(size_t)MM * NINNER];   // 128 MB silu(u) fp32 (scan)
__device__ float  g_zs  [(size_t)MM * NINNER];   // 128 MB silu(z) fp32
__device__ float  g_lam [(size_t)MM * NINNER];   // 128 MB lambda fp32
__device__ __half g_sz16[(size_t)MM * NINNER];   // 64 MB  s*silu(z) fp16 (GEMM3 A)
__device__ __half g_wi16[(size_t)2 * NINNER * DD];   // 8 MB
__device__ __half g_wd16[(size_t)NINNER * NINNER];   // 8 MB
__device__ __half g_wo16[(size_t)DD * NINNER];       // 4 MB
__device__ float  g_P[(size_t)BB * NCH * NINNER];    // 1 MB
__device__ float  g_Q[(size_t)BB * NCH * NINNER];    // 1 MB
__device__ float  g_S[(size_t)BB * NCH * NINNER];    // 1 MB

// ---------------------------------------------------------------------------
// Helpers
// ---------------------------------------------------------------------------
__device__ __forceinline__ uint32_t smem_u32(const void* p) {
    uint32_t a;
    asm("{ .reg .u64 t; cvta.to.shared.u64 t, %1; cvt.u32.u64 %0, t; }"
        : "=r"(a) : "l"(p));
    return a;
}

__device__ __forceinline__ void ldsm_x4(uint32_t* r, uint32_t addr) {
    asm volatile("ldmatrix.sync.aligned.m8n8.x4.shared.b16 {%0,%1,%2,%3}, [%4];"
        : "=r"(r[0]), "=r"(r[1]), "=r"(r[2]), "=r"(r[3]) : "r"(addr));
}

__device__ __forceinline__ void mma_f16(float* c, const uint32_t* a, const uint32_t* b) {
    asm volatile(
        "mma.sync.aligned.m16n8k16.row.col.f32.f16.f16.f32 "
        "{%0,%1,%2,%3}, {%4,%5,%6,%7}, {%8,%9}, {%0,%1,%2,%3};"
        : "+f"(c[0]), "+f"(c[1]), "+f"(c[2]), "+f"(c[3])
        : "r"(a[0]), "r"(a[1]), "r"(a[2]), "r"(a[3]), "r"(b[0]), "r"(b[1]));
}

__device__ __forceinline__ void cp16(uint32_t saddr, const void* g) {
    asm volatile("cp.async.cg.shared.global [%0], [%1], 16;" :: "r"(saddr), "l"(g));
}
#define CP_COMMIT() asm volatile("cp.async.commit_group;")
#define CP_WAIT2()  asm volatile("cp.async.wait_group 2;")

__device__ __forceinline__ uint32_t packh2(float lo, float hi) {
    __half2 t = __floats2half2_rn(lo, hi);
    return reinterpret_cast<uint32_t&>(t);
}

// ---------------------------------------------------------------------------
// Weight convert: fp32 -> fp16 (n multiple of 4)
// ---------------------------------------------------------------------------
__global__ __launch_bounds__(256) void cvt_kernel(
    const float* __restrict__ w, __half* __restrict__ o, int n4)
{
    int i = blockIdx.x * blockDim.x + threadIdx.x;
    if (i >= n4) return;
    float4 v = reinterpret_cast<const float4*>(w)[i];
    uint2 h;
    h.x = packh2(v.x, v.y);
    h.y = packh2(v.z, v.w);
    reinterpret_cast<uint2*>(o)[i] = h;
}

// ---------------------------------------------------------------------------
// RMSNorm: one block per row (1024 floats), 256 threads -> fp16
// ---------------------------------------------------------------------------
__global__ __launch_bounds__(256) void rmsnorm_kernel(
    const float* __restrict__ x, const float* __restrict__ w,
    __half* __restrict__ h16)
{
    const int row = blockIdx.x;
    const int t   = threadIdx.x;
    float4 v = reinterpret_cast<const float4*>(x + (size_t)row * DD)[t];
    float ss = v.x * v.x + v.y * v.y + v.z * v.z + v.w * v.w;

    #pragma unroll
    for (int o = 16; o > 0; o >>= 1)
        ss += __shfl_xor_sync(0xFFFFFFFFu, ss, o);

    __shared__ float wsum[8];
    if ((t & 31) == 0) wsum[t >> 5] = ss;
    __syncthreads();

    float sum = 0.f;
    #pragma unroll
    for (int i = 0; i < 8; i++) sum += wsum[i];

    const float scale = rsqrtf(sum * (1.0f / DD) + EPSV);
    const float4 wv = reinterpret_cast<const float4*>(w)[t];
    uint2 h;
    h.x = packh2(v.x * scale * wv.x, v.y * scale * wv.y);
    h.y = packh2(v.z * scale * wv.z, v.w * scale * wv.w);
    reinterpret_cast<uint2*>(h16 + (size_t)row * DD)[t] = h;
}

// ---------------------------------------------------------------------------
// mma.sync fp16 single-term NT GEMM.  C[M,N] = A[M,KD] * Bw[N,KD]^T,
// fp32 accumulate.  128x128x64 CTA tile, 8 warps (2m x 4n), warp tile 64x32
// as 4x4 m16n8k16.  cp.async 4-stage ring, one __syncthreads per 64-K tile.
// SINGLE instantiation; runtime mode switch in the epilogue.
//
// mode 0: c <  NINNER -> o16[r,c] = fp16(silu(v)), of[r,c] = silu(v)
//         c >= NINNER -> zout[r,c-NINNER] = silu(v)
// mode 1: fout[r,c] = sigmoid(v + bias[c])               (row stride NINNER)
// mode 2: fout[r,c] = resid[r,c] + v                     (row stride DD)
// ---------------------------------------------------------------------------
__global__ __launch_bounds__(256, 1) void gemm_mma(
    const __half* __restrict__ A, const __half* __restrict__ Bw,
    int KD, int mode,
    const float* __restrict__ bias, const float* __restrict__ resid,
    float* __restrict__ fout,
    __half* __restrict__ o16, float* __restrict__ of,
    float* __restrict__ zout)
{
    extern __shared__ __align__(16) char smem[];
    const uint32_t sb = smem_u32(smem);

    const int tid  = threadIdx.x;
    const int lane = tid & 31;
    const int wid  = tid >> 5;
    const int warp_m = wid >> 2;   // 0..1  (64 rows each)
    const int warp_n = wid & 3;    // 0..3  (32 cols each)
    const int bm = blockIdx.y * BM;
    const int bn = blockIdx.x * BN;
    const int NT = KD / BK;

    // Copy mapping: thread -> (row, 32-col half); 4 cp16 per array
    const int srow = tid >> 1;
    const int scol = (tid & 1) * 32;
    const __half* ga = A  + (size_t)(bm + srow) * KD + scol;
    const __half* gb = Bw + (size_t)(bn + srow) * KD + scol;
    const uint32_t s_off = (uint32_t)(srow * LDSS + scol) * 2;

    // ldmatrix per-lane addressing (verified mapping, R6)
    const int a_row0 = warp_m * 64 + (lane & 15);
    const int a_kadd = (lane >> 4) * 8;
    const int b_row0 = warp_n * 32 + ((lane >> 4) & 1) * 8 + (lane & 7);
    const int b_kadd = ((lane >> 3) & 1) * 8;

    float acc[4][4][4];
    #pragma unroll
    for (int i = 0; i < 4; i++)
        #pragma unroll
        for (int j = 0; j < 4; j++)
            #pragma unroll
            for (int q = 0; q < 4; q++) acc[i][j][q] = 0.f;

    // issue copies for tile kt into stage (each array: 4 cp16 = 64B/thread)
    auto issue = [&](int stage, int kt) {
        const int k0 = kt * BK;
        const uint32_t st = sb + stage * STAGE_BYTES + s_off;
        #pragma unroll
        for (int q = 0; q < 4; q++) {
            cp16(st + q * 16,             ga + k0 + q * 8);
            cp16(st + ARR_BYTES + q * 16, gb + k0 + q * 8);
        }
    };

    issue(0, 0); CP_COMMIT();
    issue(1, 1); CP_COMMIT();
    issue(2, 2); CP_COMMIT();

    int stage = 0;
    for (int kt = 0; kt < NT; kt++) {
        CP_WAIT2();                 // stage kt resident
        __syncthreads();

        if (kt + 3 < NT) {
            int ns = stage + 3; if (ns >= NSTAGE) ns -= NSTAGE;
            issue(ns, kt + 3);
        }
        CP_COMMIT();

        const uint32_t a_b = sb + stage * STAGE_BYTES;
        const uint32_t b_b = a_b + ARR_BYTES;

        #pragma unroll
        for (int ks = 0; ks < 4; ks++) {
            uint32_t bf[4][2];
            #pragma unroll
            for (int pair = 0; pair < 2; pair++) {
                const uint32_t off =
                    2u * ((b_row0 + pair * 16) * LDSS + ks * 16 + b_kadd);
                uint32_t r[4];
                ldsm_x4(r, b_b + off);
                bf[pair * 2][0] = r[0]; bf[pair * 2][1] = r[1];
                bf[pair * 2 + 1][0] = r[2]; bf[pair * 2 + 1][1] = r[3];
            }
            #pragma unroll
            for (int mt = 0; mt < 4; mt++) {
                const uint32_t off =
                    2u * ((a_row0 + mt * 16) * LDSS + ks * 16 + a_kadd);
                uint32_t af[4];
                ldsm_x4(af, a_b + off);
                #pragma unroll
                for (int nt = 0; nt < 4; nt++)
                    mma_f16(acc[mt][nt], af, bf[nt]);
            }
        }

        stage++; if (stage >= NSTAGE) stage = 0;
    }

    // Epilogue straight from accumulators (uniform runtime mode branch).
    const int er = bm + warp_m * 64 + (lane >> 2);
    const int ec = bn + warp_n * 32 + (lane & 3) * 2;

    #pragma unroll
    for (int mt = 0; mt < 4; mt++) {
        #pragma unroll
        for (int nt = 0; nt < 4; nt++) {
            #pragma unroll
            for (int half = 0; half < 2; half++) {
                const int r = er + mt * 16 + half * 8;
                const int c = ec + nt * 8;
                float v0 = acc[mt][nt][half * 2 + 0];
                float v1 = acc[mt][nt][half * 2 + 1];
                if (mode == 0) {
                    float s0 = v0 / (1.0f + expf(-v0));
                    float s1 = v1 / (1.0f + expf(-v1));
                    if (bn < NINNER) {
                        *reinterpret_cast<uint32_t*>(o16 + (size_t)r * NINNER + c) =
                            packh2(s0, s1);
                        *reinterpret_cast<float2*>(of + (size_t)r * NINNER + c) =
                            make_float2(s0, s1);
                    } else {
                        *reinterpret_cast<float2*>(zout + (size_t)r * NINNER + (c - NINNER)) =
                            make_float2(s0, s1);
                    }
                } else if (mode == 1) {
                    float2 bv = *reinterpret_cast<const float2*>(bias + c);
                    float2 o;
                    o.x = 1.0f / (1.0f + expf(-(v0 + bv.x)));
                    o.y = 1.0f / (1.0f + expf(-(v1 + bv.y)));
                    *reinterpret_cast<float2*>(fout + (size_t)r * NINNER + c) = o;
                } else {
                    float2 rv = *reinterpret_cast<const float2*>(resid + (size_t)r * DD + c);
                    float2 o;
                    o.x = rv.x + v0;
                    o.y = rv.y + v1;
                    *reinterpret_cast<float2*>(fout + (size_t)r * DD + c) = o;
                }
            }
        }
    }
}

// ---------------------------------------------------------------------------
// Parallel chunked scan.  s_k = u_k + lam_k*(s_{k-1}-u_k)  over K=2048,
// split into NCH=16 chunks of 128.  Affine composition: s_out = P*s_in + Q.
// ---------------------------------------------------------------------------
// Phase 1: per (b, chunk, j) compute P = prod(lam), Q = chunk scan from 0.
__global__ __launch_bounds__(256) void scan_p1(
    const float* __restrict__ lam, const float* __restrict__ uf,
    float* __restrict__ Pb, float* __restrict__ Qb)
{
    const int idx = blockIdx.x * blockDim.x + threadIdx.x;
    const int j   = idx & (NINNER - 1);
    const int bc  = idx >> 11;              // b * NCH + c
    const int b   = bc >> 4;
    const int c   = bc & (NCH - 1);
    size_t off = ((size_t)(b * KK + c * CHUNK)) * NINNER + j;
    float P = 1.f, Q = 0.f;
    #pragma unroll 8
    for (int k = 0; k < CHUNK; k++) {
        const float l  = __ldg(lam + off);
        const float uu = __ldg(uf + off);
        Q = fmaf(l, Q - uu, uu);
        P *= l;
        off += NINNER;
    }
    Pb[idx] = P;
    Qb[idx] = Q;
}

// Phase 2: per (b, j) scan the 16 chunk summaries -> entry state per chunk.
__global__ __launch_bounds__(256) void scan_p2(
    const float* __restrict__ Pb, const float* __restrict__ Qb,
    float* __restrict__ Sb)
{
    const int idx = blockIdx.x * blockDim.x + threadIdx.x;  // 0..16383
    const int b = idx >> 11;
    const int j = idx & (NINNER - 1);
    float s = 0.f;
    #pragma unroll
    for (int c = 0; c < NCH; c++) {
        const size_t o = ((size_t)(b * NCH + c)) * NINNER + j;
        Sb[o] = s;
        s = fmaf(Pb[o], s, Qb[o]);
    }
}

// Phase 3: replay each chunk with its entry state; write s*silu(z) fp16.
__global__ __launch_bounds__(256) void scan_p3(
    const float* __restrict__ lam, const float* __restrict__ uf,
    const float* __restrict__ zs, const float* __restrict__ Sb,
    __half* __restrict__ sz16)
{
    const int idx = blockIdx.x * blockDim.x + threadIdx.x;
    const int j   = idx & (NINNER - 1);
    const int bc  = idx >> 11;
    const int b   = bc >> 4;
    const int c   = bc & (NCH - 1);
    size_t off = ((size_t)(b * KK + c * CHUNK)) * NINNER + j;
    float s = Sb[idx];
    #pragma unroll 8
    for (int k = 0; k < CHUNK; k++) {
        const float l  = __ldg(lam + off);
        const float uu = __ldg(uf + off);
        const float zz = __ldg(zs + off);
        s = fmaf(l, s - uu, uu);
        sz16[off] = __float2half_rn(s * zz);
        off += NINNER;
    }
}

// ---------------------------------------------------------------------------
// Launch
// ---------------------------------------------------------------------------
extern "C" void kernel_launch(void* const* d_in, const int* in_sizes, int n_in,
                              void* d_out, int out_size)
{
    const float* x      = (const float*)d_in[0];
    const float* w_norm = (const float*)d_in[1];
    const float* W_in   = (const float*)d_in[2];   // [2*NINNER, DD]
    const float* W_dt   = (const float*)d_in[3];   // [NINNER, NINNER]
    const float* b_dt   = (const float*)d_in[4];   // [NINNER]
    const float* W_out  = (const float*)d_in[5];   // [DD, NINNER]
    float* out = (float*)d_out;

    __half *h16, *u16, *sz16, *wi16, *wd16, *wo16;
    float *uf, *zs, *lam, *Pb, *Qb, *Sb;
    cudaGetSymbolAddress((void**)&h16,  g_h16);
    cudaGetSymbolAddress((void**)&u16,  g_u16);
    cudaGetSymbolAddress((void**)&uf,   g_uf);
    cudaGetSymbolAddress((void**)&zs,   g_zs);
    cudaGetSymbolAddress((void**)&lam,  g_lam);
    cudaGetSymbolAddress((void**)&sz16, g_sz16);
    cudaGetSymbolAddress((void**)&wi16, g_wi16);
    cudaGetSymbolAddress((void**)&wd16, g_wd16);
    cudaGetSymbolAddress((void**)&wo16, g_wo16);
    cudaGetSymbolAddress((void**)&Pb,   g_P);
    cudaGetSymbolAddress((void**)&Qb,   g_Q);
    cudaGetSymbolAddress((void**)&Sb,   g_S);

    cudaFuncSetAttribute(gemm_mma, cudaFuncAttributeMaxDynamicSharedMemorySize, SMEM_TOTAL);

    // 0. Convert weights to fp16
    cvt_kernel<<<(2 * NINNER * DD / 4 + 255) / 256, 256>>>(W_in,  wi16, 2 * NINNER * DD / 4);
    cvt_kernel<<<(NINNER * NINNER / 4 + 255) / 256, 256>>>(W_dt,  wd16, NINNER * NINNER / 4);
    cvt_kernel<<<(DD * NINNER / 4 + 255) / 256, 256>>>(W_out, wo16, DD * NINNER / 4);

    // 1. RMSNorm -> h fp16
    rmsnorm_kernel<<<MM, 256>>>(x, w_norm, h16);

    // 2. uv = h @ W_in^T ; split + silu   (M=16384, N=4096, KD=1024)
    {
        dim3 grid((2 * NINNER) / BN, MM / BM);
        gemm_mma<<<grid, 256, SMEM_TOTAL>>>(h16, wi16, DD, 0,
                                            nullptr, nullptr, nullptr, u16, uf, zs);
    }

    // 3. lam = sigmoid(u @ W_dt^T + b_dt)   (M=16384, N=2048, KD=2048)
    {
        dim3 grid(NINNER / BN, MM / BM);
        gemm_mma<<<grid, 256, SMEM_TOTAL>>>(u16, wd16, NINNER, 1,
                                            b_dt, nullptr, lam, nullptr, nullptr, nullptr);
    }

    // 4. parallel chunked scan -> sz fp16
    scan_p1<<<BB * NCH * NINNER / 256, 256>>>(lam, uf, Pb, Qb);
    scan_p2<<<BB * NINNER / 256, 256>>>(Pb, Qb, Sb);
    scan_p3<<<BB * NCH * NINNER / 256, 256>>>(lam, uf, zs, Sb, sz16);

    // 5. y = sz @ W_out^T + x   (M=16384, N=1024, KD=2048)
    {
        dim3 grid(DD / BN, MM / BM);
        gemm_mma<<<grid, 256, SMEM_TOTAL>>>(sz16, wo16, NINNER, 2,
                                            nullptr, x, out, nullptr, nullptr, nullptr);
    }
}